// round 1
// baseline (speedup 1.0000x reference)
#include <cuda_runtime.h>

// Problem constants (fixed by the reference):
//   x: [B, 96, 128, 128] fp32, B derived from in_sizes[0]
//   depthwise 3x3, stride 1, pad 1
#define C_DIM 96
#define HW 128
#define PLANE (HW * HW)          // 16384
#define CR 24                    // C_DIM / 4
#define WDYN_PER_B (C_DIM * 9)   // 864
#define BN_EPS 1e-5f
#define MAX_B 64

// Scratch (allocation-free rule: __device__ globals)
__device__ float g_pooled[MAX_B * C_DIM];
__device__ float g_wdyn[MAX_B * WDYN_PER_B];

// ---------------------------------------------------------------------------
// Kernel 1: global average pool over each (b,c) plane.
// One block per plane, 256 threads, float4 loads.
// ---------------------------------------------------------------------------
__global__ __launch_bounds__(256) void pool_kernel(const float* __restrict__ x,
                                                   float* __restrict__ pooled) {
    const int plane = blockIdx.x;
    const float4* xp = reinterpret_cast<const float4*>(x + (size_t)plane * PLANE);
    float s = 0.f;
#pragma unroll 4
    for (int i = threadIdx.x; i < PLANE / 4; i += 256) {
        float4 v = xp[i];
        s += (v.x + v.y) + (v.z + v.w);
    }
#pragma unroll
    for (int o = 16; o > 0; o >>= 1) s += __shfl_xor_sync(0xffffffffu, s, o);

    __shared__ float ws[8];
    if ((threadIdx.x & 31) == 0) ws[threadIdx.x >> 5] = s;
    __syncthreads();
    if (threadIdx.x < 8) {
        float t = ws[threadIdx.x];
#pragma unroll
        for (int o = 4; o > 0; o >>= 1) t += __shfl_xor_sync(0xffu, t, o);
        if (threadIdx.x == 0) pooled[plane] = t * (1.f / (float)PLANE);
    }
}

// ---------------------------------------------------------------------------
// Kernel 2: dynamic weight generation. One block per batch sample.
//   h1 = sigmoid(BN(pooled @ w1^T));  wdyn = h1 @ w2^T + b2
// ---------------------------------------------------------------------------
__global__ __launch_bounds__(256) void weight_kernel(
    const float* __restrict__ pooled,
    const float* __restrict__ w1,      // [CR, C_DIM]
    const float* __restrict__ gamma,
    const float* __restrict__ beta,
    const float* __restrict__ rmean,
    const float* __restrict__ rvar,
    const float* __restrict__ w2,      // [WDYN_PER_B, CR]
    const float* __restrict__ b2,
    float* __restrict__ wdyn) {
    const int b = blockIdx.x;
    __shared__ float p[C_DIM];
    __shared__ float h1[CR];
    const int tid = threadIdx.x;

    if (tid < C_DIM) p[tid] = pooled[b * C_DIM + tid];
    __syncthreads();

    if (tid < CR) {
        float s = 0.f;
        const float* wr = w1 + tid * C_DIM;
#pragma unroll 8
        for (int c = 0; c < C_DIM; c++) s += p[c] * wr[c];
        s = (s - rmean[tid]) * rsqrtf(rvar[tid] + BN_EPS) * gamma[tid] + beta[tid];
        h1[tid] = 1.f / (1.f + __expf(-s));
    }
    __syncthreads();

    for (int o = tid; o < WDYN_PER_B; o += 256) {
        float s = b2[o];
        const float* wr = w2 + o * CR;
#pragma unroll
        for (int j = 0; j < CR; j++) s += h1[j] * wr[j];
        wdyn[b * WDYN_PER_B + o] = s;
    }
}

// ---------------------------------------------------------------------------
// Kernel 3: per-sample depthwise 3x3 conv, pad 1, stride 1.
// Grid: (B*C planes, HW/ROWS row-tiles). Block (32,8) = 256 threads.
// Shared tile: (ROWS+2) x TW floats; tile col 0 maps to x col -1 (zero halo).
// Each thread computes 4 contiguous outputs (one float4 store).
// ---------------------------------------------------------------------------
#define ROWS 8
#define TW 136   // 130 used (cols -1..128), padded to 16B multiple

__global__ __launch_bounds__(256) void dwconv_kernel(
    const float* __restrict__ x,
    const float* __restrict__ wdyn,
    const float* __restrict__ bias,
    float* __restrict__ out) {
    const int plane = blockIdx.x;          // b*C + c
    const int ch = plane % C_DIM;
    const int row0 = blockIdx.y * ROWS;

    __shared__ float tile[ROWS + 2][TW];

    const float* xp = x + (size_t)plane * PLANE;
    float* op = out + (size_t)plane * PLANE;

    // per-channel dynamic 3x3 weights (broadcast load, L1-cached)
    float w[9];
    const float* wp = wdyn + (size_t)plane * 9;
#pragma unroll
    for (int i = 0; i < 9; i++) w[i] = __ldg(wp + i);
    const float bv = __ldg(bias + ch);

    const int tid = threadIdx.y * 32 + threadIdx.x;

    // Load (ROWS+2) rows x 128 cols as float4; zero rows outside the plane.
    for (int i = tid; i < (ROWS + 2) * 32; i += 256) {
        const int r  = i >> 5;       // 0..ROWS+1
        const int cq = i & 31;       // float4 index within row
        const int gr = row0 - 1 + r;
        float4 v = make_float4(0.f, 0.f, 0.f, 0.f);
        if ((unsigned)gr < (unsigned)HW)
            v = *reinterpret_cast<const float4*>(xp + gr * HW + cq * 4);
        float* t = &tile[r][1 + cq * 4];
        t[0] = v.x; t[1] = v.y; t[2] = v.z; t[3] = v.w;
    }
    // zero column halos (x col -1 at tile col 0, x col 128 at tile col 129)
    if (tid < 2 * (ROWS + 2)) {
        const int r = tid >> 1;
        tile[r][(tid & 1) ? 129 : 0] = 0.f;
    }
    __syncthreads();

    const int r  = threadIdx.y;       // output row within tile
    const int cx = threadIdx.x * 4;   // output col base

    float a0 = 0.f, a1 = 0.f, a2 = 0.f, a3 = 0.f;
#pragma unroll
    for (int dy = 0; dy < 3; dy++) {
        // tile col (j + dx) corresponds to x col (j - 1 + dx); need cols cx..cx+5
        const float4 v0 = *reinterpret_cast<const float4*>(&tile[r + dy][cx]);       // LDS.128
        const float2 v1 = *reinterpret_cast<const float2*>(&tile[r + dy][cx + 4]);   // LDS.64
        const float w0 = w[dy * 3 + 0], w1 = w[dy * 3 + 1], w2 = w[dy * 3 + 2];
        a0 += v0.x * w0 + v0.y * w1 + v0.z * w2;
        a1 += v0.y * w0 + v0.z * w1 + v0.w * w2;
        a2 += v0.z * w0 + v0.w * w1 + v1.x * w2;
        a3 += v0.w * w0 + v1.x * w1 + v1.y * w2;
    }

    float4 o;
    o.x = a0 + bv; o.y = a1 + bv; o.z = a2 + bv; o.w = a3 + bv;
    *reinterpret_cast<float4*>(op + (row0 + r) * HW + cx) = o;
}

// ---------------------------------------------------------------------------
// Launch
// ---------------------------------------------------------------------------
extern "C" void kernel_launch(void* const* d_in, const int* in_sizes, int n_in,
                              void* d_out, int out_size) {
    const float* x     = (const float*)d_in[0];
    const float* w1    = (const float*)d_in[1];
    const float* gamma = (const float*)d_in[2];
    const float* beta  = (const float*)d_in[3];
    const float* rmean = (const float*)d_in[4];
    const float* rvar  = (const float*)d_in[5];
    const float* w2    = (const float*)d_in[6];
    const float* b2    = (const float*)d_in[7];
    const float* bias  = (const float*)d_in[8];
    float* out = (float*)d_out;

    const int B = in_sizes[0] / (C_DIM * PLANE);
    const int planes = B * C_DIM;

    float* pooled;
    float* wdyn;
    cudaGetSymbolAddress((void**)&pooled, g_pooled);
    cudaGetSymbolAddress((void**)&wdyn, g_wdyn);

    pool_kernel<<<planes, 256>>>(x, pooled);
    weight_kernel<<<B, 256>>>(pooled, w1, gamma, beta, rmean, rvar, w2, b2, wdyn);
    dim3 grid(planes, HW / ROWS);
    dim3 block(32, ROWS);
    dwconv_kernel<<<grid, block>>>(x, wdyn, bias, out);
}

// round 3
// speedup vs baseline: 1.2410x; 1.2410x over previous
#include <cuda_runtime.h>

// Problem constants (fixed by the reference):
//   x: [B, 96, 128, 128] fp32, depthwise 3x3, stride 1, pad 1
#define C_DIM 96
#define HW 128
#define PLANE (HW * HW)          // 16384
#define CR 24                    // C_DIM / 4
#define WDYN_PER_B (C_DIM * 9)   // 864
#define BN_EPS 1e-5f
#define MAX_B 64

// Scratch (allocation-free rule: __device__ globals)
__device__ float g_pooled[MAX_B * C_DIM];
__device__ float g_wdyn[MAX_B * WDYN_PER_B];

// ---------------------------------------------------------------------------
// Kernel 1: global average pool over each (b,c) plane.
// One block per plane, 256 threads, float4 loads.  (measured 80.9% DRAM — keep)
// ---------------------------------------------------------------------------
__global__ __launch_bounds__(256) void pool_kernel(const float* __restrict__ x,
                                                   float* __restrict__ pooled) {
    const int plane = blockIdx.x;
    const float4* xp = reinterpret_cast<const float4*>(x + (size_t)plane * PLANE);
    float s = 0.f;
#pragma unroll 4
    for (int i = threadIdx.x; i < PLANE / 4; i += 256) {
        float4 v = xp[i];
        s += (v.x + v.y) + (v.z + v.w);
    }
#pragma unroll
    for (int o = 16; o > 0; o >>= 1) s += __shfl_xor_sync(0xffffffffu, s, o);

    __shared__ float ws[8];
    if ((threadIdx.x & 31) == 0) ws[threadIdx.x >> 5] = s;
    __syncthreads();
    if (threadIdx.x < 8) {
        float t = ws[threadIdx.x];
#pragma unroll
        for (int o = 4; o > 0; o >>= 1) t += __shfl_xor_sync(0xffu, t, o);
        if (threadIdx.x == 0) pooled[plane] = t * (1.f / (float)PLANE);
    }
}

// ---------------------------------------------------------------------------
// Kernel 2: dynamic weight generation. One block per batch sample.
// ---------------------------------------------------------------------------
__global__ __launch_bounds__(256) void weight_kernel(
    const float* __restrict__ pooled,
    const float* __restrict__ w1,      // [CR, C_DIM]
    const float* __restrict__ gamma,
    const float* __restrict__ beta,
    const float* __restrict__ rmean,
    const float* __restrict__ rvar,
    const float* __restrict__ w2,      // [WDYN_PER_B, CR]
    const float* __restrict__ b2,
    float* __restrict__ wdyn) {
    const int b = blockIdx.x;
    __shared__ float p[C_DIM];
    __shared__ float h1[CR];
    const int tid = threadIdx.x;

    if (tid < C_DIM) p[tid] = pooled[b * C_DIM + tid];
    __syncthreads();

    if (tid < CR) {
        float s = 0.f;
        const float* wr = w1 + tid * C_DIM;
#pragma unroll 8
        for (int c = 0; c < C_DIM; c++) s += p[c] * wr[c];
        s = (s - rmean[tid]) * rsqrtf(rvar[tid] + BN_EPS) * gamma[tid] + beta[tid];
        h1[tid] = 1.f / (1.f + __expf(-s));
    }
    __syncthreads();

    for (int o = tid; o < WDYN_PER_B; o += 256) {
        float s = b2[o];
        const float* wr = w2 + o * CR;
#pragma unroll
        for (int j = 0; j < CR; j++) s += h1[j] * wr[j];
        wdyn[b * WDYN_PER_B + o] = s;
    }
}

// ---------------------------------------------------------------------------
// Kernel 3: per-sample depthwise 3x3 conv, pad 1, stride 1 — warp-per-strip,
// register sliding window, shfl for column neighbors. No smem, no syncthreads,
// ~6% halo read amplification (2 rows per 32-row strip).
// Grid: planes; block (32, STRIPS): warp s handles rows [32s, 32s+32).
// ---------------------------------------------------------------------------
#define STRIPS 4
#define SROWS (HW / STRIPS)   // 32

struct Row { float4 v; float l, r; };

__device__ __forceinline__ Row mkrow(float4 v, int lane) {
    Row rr; rr.v = v;
    float l = __shfl_up_sync(0xffffffffu, v.w, 1);
    float r = __shfl_down_sync(0xffffffffu, v.x, 1);
    rr.l = (lane == 0) ? 0.f : l;
    rr.r = (lane == 31) ? 0.f : r;
    return rr;
}

__global__ __launch_bounds__(32 * STRIPS) void dwconv_kernel(
    const float* __restrict__ x,
    const float* __restrict__ wdyn,
    const float* __restrict__ bias,
    float* __restrict__ out) {
    const int plane = blockIdx.x;          // b*C + c
    const int ch = plane % C_DIM;
    const int lane = threadIdx.x;
    const int row0 = threadIdx.y * SROWS;

    const float* xp = x + (size_t)plane * PLANE;
    float* op = out + (size_t)plane * PLANE;

    // per-channel dynamic 3x3 weights (broadcast, L1-cached)
    float w[9];
    const float* wp = wdyn + (size_t)plane * 9;
#pragma unroll
    for (int i = 0; i < 9; i++) w[i] = __ldg(wp + i);
    const float bv = __ldg(bias + ch);

    auto loadrow = [&](int r) -> float4 {
        if ((unsigned)r < (unsigned)HW)
            return reinterpret_cast<const float4*>(xp + r * HW)[lane];
        return make_float4(0.f, 0.f, 0.f, 0.f);
    };

    Row A = mkrow(loadrow(row0 - 1), lane);
    Row B = mkrow(loadrow(row0),     lane);
    Row C = mkrow(loadrow(row0 + 1), lane);

#pragma unroll 4
    for (int i = 0; i < SROWS; i++) {
        // prefetch next row early (one-row software pipeline)
        float4 nv = loadrow(row0 + 2 + i);

        float a0 = bv, a1 = bv, a2 = bv, a3 = bv;
#pragma unroll
        for (int dy = 0; dy < 3; dy++) {
            const Row& R = (dy == 0) ? A : (dy == 1) ? B : C;
            const float w0 = w[dy * 3 + 0], w1 = w[dy * 3 + 1], w2 = w[dy * 3 + 2];
            a0 += R.l   * w0 + R.v.x * w1 + R.v.y * w2;
            a1 += R.v.x * w0 + R.v.y * w1 + R.v.z * w2;
            a2 += R.v.y * w0 + R.v.z * w1 + R.v.w * w2;
            a3 += R.v.z * w0 + R.v.w * w1 + R.r   * w2;
        }
        float4 o; o.x = a0; o.y = a1; o.z = a2; o.w = a3;
        reinterpret_cast<float4*>(op + (row0 + i) * HW)[lane] = o;

        A = B; B = C; C = mkrow(nv, lane);
    }
}

// ---------------------------------------------------------------------------
// Launch
// ---------------------------------------------------------------------------
extern "C" void kernel_launch(void* const* d_in, const int* in_sizes, int n_in,
                              void* d_out, int out_size) {
    const float* x     = (const float*)d_in[0];
    const float* w1    = (const float*)d_in[1];
    const float* gamma = (const float*)d_in[2];
    const float* beta  = (const float*)d_in[3];
    const float* rmean = (const float*)d_in[4];
    const float* rvar  = (const float*)d_in[5];
    const float* w2    = (const float*)d_in[6];
    const float* b2    = (const float*)d_in[7];
    const float* bias  = (const float*)d_in[8];
    float* out = (float*)d_out;

    const int B = in_sizes[0] / (C_DIM * PLANE);
    const int planes = B * C_DIM;

    float* pooled;
    float* wdyn;
    cudaGetSymbolAddress((void**)&pooled, g_pooled);
    cudaGetSymbolAddress((void**)&wdyn, g_wdyn);

    pool_kernel<<<planes, 256>>>(x, pooled);
    weight_kernel<<<B, 256>>>(pooled, w1, gamma, beta, rmean, rvar, w2, b2, wdyn);
    dim3 block(32, STRIPS);
    dwconv_kernel<<<planes, block>>>(x, wdyn, bias, out);
}